// round 16
// baseline (speedup 1.0000x reference)
#include <cuda_runtime.h>
#include <cuda_bf16.h>
#include <mma.h>
#include <stdint.h>

using namespace nvcuda;

// Problem constants (fixed benchmark): N=1e6, IN_C=OUT_C=64, FEAT_C=128, G=4096
#define N_MAX 1000000
#define G_MAX 4096

__device__ int      d_count[G_MAX];
__device__ int      d_offsets[G_MAX + 1];
__device__ int      d_rank[N_MAX];
__device__ int      d_order[N_MAX];
__device__ float    d_mu[G_MAX * 64];
__device__ float    d_sig[G_MAX * 64];
__device__ uint32_t d_Wh32[2048];          // bf16 hi image of W [64k][64n] as u32 pairs
__device__ uint32_t d_Wl32[2048];          // bf16 lo image
__device__ float    d_M[(size_t)G_MAX * 4096];   // per-group X^T X (64MB)
__device__ float    d_xsum[G_MAX * 64];
__device__ float    d_scale[G_MAX * 64];
__device__ float    d_shift[G_MAX * 64];

// ---------------------------------------------------------------------------
// Preprocessing
// ---------------------------------------------------------------------------
__global__ void musig_init_kernel(const float* __restrict__ feat,
                                  const float* __restrict__ Wmu, const float* __restrict__ bmu,
                                  const float* __restrict__ Wsg, const float* __restrict__ bsg,
                                  const float* __restrict__ Wfc, int G) {
    int gid = blockIdx.x * blockDim.x + threadIdx.x;
    if (gid < G) d_count[gid] = 0;
    if (gid < 2048) {  // pair (k, 2j)/(k, 2j+1)
        int k = gid >> 5, j = gid & 31;
        float w0 = Wfc[k * 64 + 2 * j];
        float w1 = Wfc[k * 64 + 2 * j + 1];
        __nv_bfloat16 h0 = __float2bfloat16(w0);
        __nv_bfloat16 h1 = __float2bfloat16(w1);
        __nv_bfloat16 l0 = __float2bfloat16(w0 - __bfloat162float(h0));
        __nv_bfloat16 l1 = __float2bfloat16(w1 - __bfloat162float(h1));
        d_Wh32[gid] = (uint32_t)__bfloat16_as_ushort(h0) | ((uint32_t)__bfloat16_as_ushort(h1) << 16);
        d_Wl32[gid] = (uint32_t)__bfloat16_as_ushort(l0) | ((uint32_t)__bfloat16_as_ushort(l1) << 16);
    }

    __shared__ float sF[4][128];
    int t  = threadIdx.x;
    int g0 = blockIdx.x * 4;
    for (int i = t; i < 512; i += 256) {
        int gl = i >> 7, k = i & 127;
        int g  = g0 + gl;
        sF[gl][k] = (g < G) ? feat[(size_t)g * 128 + k] : 0.f;
    }
    __syncthreads();
    int gl = t >> 6, c = t & 63;
    int g  = g0 + gl;
    if (g >= G) return;
    float am = bmu[c], as = bsg[c];
#pragma unroll 4
    for (int k = 0; k < 128; k++) {
        float f = sF[gl][k];
        am = fmaf(f, Wmu[k * 64 + c], am);
        as = fmaf(f, Wsg[k * 64 + c], as);
    }
    d_mu[(size_t)g * 64 + c]  = am;
    d_sig[(size_t)g * 64 + c] = as;
}

__global__ void hist_kernel(const int* __restrict__ seg, int n) {
    int i = blockIdx.x * blockDim.x + threadIdx.x;
    int base = i * 4;
    if (base + 3 < n) {
        int4 s = *reinterpret_cast<const int4*>(seg + base);
        int r0 = atomicAdd(&d_count[s.x], 1);
        int r1 = atomicAdd(&d_count[s.y], 1);
        int r2 = atomicAdd(&d_count[s.z], 1);
        int r3 = atomicAdd(&d_count[s.w], 1);
        *reinterpret_cast<int4*>(d_rank + base) = make_int4(r0, r1, r2, r3);
    } else {
        for (int j = base; j < n; j++)
            d_rank[j] = atomicAdd(&d_count[seg[j]], 1);
    }
}

__global__ void scan_kernel(int G) {
    __shared__ int wsum[32];
    __shared__ int wpre[32];
    const unsigned full = 0xffffffffu;
    int t = threadIdx.x, lane = t & 31, w = t >> 5;
    int v[4];
    int s = 0;
#pragma unroll
    for (int i = 0; i < 4; i++) {
        int g = 4 * t + i;
        v[i] = (g < G) ? d_count[g] : 0;
        s += v[i];
    }
    int sc = s;
#pragma unroll
    for (int off = 1; off < 32; off <<= 1) {
        int o = __shfl_up_sync(full, sc, off);
        if (lane >= off) sc += o;
    }
    if (lane == 31) wsum[w] = sc;
    __syncthreads();
    if (w == 0) {
        int ws = wsum[lane];
        int p = ws;
#pragma unroll
        for (int off = 1; off < 32; off <<= 1) {
            int o = __shfl_up_sync(full, p, off);
            if (lane >= off) p += o;
        }
        wpre[lane] = p - ws;
    }
    __syncthreads();
    int excl = wpre[w] + sc - s;
#pragma unroll
    for (int i = 0; i < 4; i++) {
        int g = 4 * t + i;
        if (g < G) {
            d_offsets[g] = excl;
            excl += v[i];
        }
    }
    if (t == 1023) d_offsets[G] = excl;
}

__global__ void scatter_kernel(const int* __restrict__ seg, int n) {
    int i = blockIdx.x * blockDim.x + threadIdx.x;
    int base = i * 4;
    if (base + 3 < n) {
        int4 s = *reinterpret_cast<const int4*>(seg + base);
        int4 r = *reinterpret_cast<const int4*>(d_rank + base);
        d_order[d_offsets[s.x] + r.x] = base;
        d_order[d_offsets[s.y] + r.y] = base + 1;
        d_order[d_offsets[s.z] + r.z] = base + 2;
        d_order[d_offsets[s.w] + r.w] = base + 3;
    } else {
        for (int j = base; j < n; j++)
            d_order[d_offsets[seg[j]] + d_rank[j]] = j;
    }
}

// ---------------------------------------------------------------------------
// Common: convert a staged x row-half into bf16 hi/lo smem (stride LDA=72)
// ---------------------------------------------------------------------------
#define LDA 72

__device__ __forceinline__ void cvt_store_half(char* Ah, char* Al, int sr, int sq,
                                               const float4 v[8]) {
    uint32_t uh[16], ul[16];
#pragma unroll
    for (int i = 0; i < 8; i++) {
        float f0 = v[i].x, f1 = v[i].y, f2 = v[i].z, f3 = v[i].w;
        __nv_bfloat16 h0 = __float2bfloat16(f0), h1 = __float2bfloat16(f1);
        __nv_bfloat16 h2 = __float2bfloat16(f2), h3 = __float2bfloat16(f3);
        __nv_bfloat16 l0 = __float2bfloat16(f0 - __bfloat162float(h0));
        __nv_bfloat16 l1 = __float2bfloat16(f1 - __bfloat162float(h1));
        __nv_bfloat16 l2 = __float2bfloat16(f2 - __bfloat162float(h2));
        __nv_bfloat16 l3 = __float2bfloat16(f3 - __bfloat162float(h3));
        uh[2 * i]     = (uint32_t)__bfloat16_as_ushort(h0) | ((uint32_t)__bfloat16_as_ushort(h1) << 16);
        uh[2 * i + 1] = (uint32_t)__bfloat16_as_ushort(h2) | ((uint32_t)__bfloat16_as_ushort(h3) << 16);
        ul[2 * i]     = (uint32_t)__bfloat16_as_ushort(l0) | ((uint32_t)__bfloat16_as_ushort(l1) << 16);
        ul[2 * i + 1] = (uint32_t)__bfloat16_as_ushort(l2) | ((uint32_t)__bfloat16_as_ushort(l3) << 16);
    }
    int b2 = sr * (LDA * 2) + 64 * sq;
#pragma unroll
    for (int i = 0; i < 4; i++) {
        *reinterpret_cast<uint4*>(Ah + b2 + 16 * i) =
            make_uint4(uh[4 * i], uh[4 * i + 1], uh[4 * i + 2], uh[4 * i + 3]);
        *reinterpret_cast<uint4*>(Al + b2 + 16 * i) =
            make_uint4(ul[4 * i], ul[4 * i + 1], ul[4 * i + 2], ul[4 * i + 3]);
    }
}

typedef wmma::fragment<wmma::matrix_a, 16, 16, 16, __nv_bfloat16, wmma::row_major> FragA;
typedef wmma::fragment<wmma::matrix_a, 16, 16, 16, __nv_bfloat16, wmma::col_major> FragAT;
typedef wmma::fragment<wmma::matrix_b, 16, 16, 16, __nv_bfloat16, wmma::row_major> FragB;
typedef wmma::fragment<wmma::accumulator, 16, 16, 16, float> FragC;

// ---------------------------------------------------------------------------
// Kernel 1: per-group second moment M = X^T X (3-split) + x_sum.
// CTA per group, 256 threads, 37KB smem -> ~5 CTAs/SM. Scattered x gather is
// the ONLY scattered traffic in the whole pipeline.
// smem: Ah 128*72*2=18432, Al 18432, xs 4*64*4=1024  -> 37888
// ---------------------------------------------------------------------------
#define MOM_SMEM 37888

__global__ __launch_bounds__(256, 4) void moment_kernel(const float* __restrict__ x) {
    extern __shared__ char smem[];
    char*  Ah = smem;
    char*  Al = smem + 18432;
    float* xs = reinterpret_cast<float*>(smem + 36864);

    int t = threadIdx.x, w = t >> 5;
    int g   = blockIdx.x;
    int off = d_offsets[g];
    int cnt = d_offsets[g + 1] - off;
    if (cnt == 0) return;

    int sr = t >> 1, sq = t & 1;      // staging coords
    int rp = t >> 6, cc = t & 63;     // xsum coords
    int wi = w >> 1, wj = (w & 1) * 2;  // warp's M tiles: (wi, wj), (wi, wj+1)

    FragC m0, m1;
    wmma::fill_fragment(m0, 0.f);
    wmma::fill_fragment(m1, 0.f);
    float xacc = 0.f;

    int nch = (cnt + 127) >> 7;
    for (int c = 0; c < nch; c++) {
        int base = c << 7;
        // stage 128 gathered rows (zero-padded past cnt)
        {
            float4 v[8];
            int grow = base + sr;
            if (grow < cnt) {
                int gi = __ldg(&d_order[off + grow]);
                const float4* xr = reinterpret_cast<const float4*>(x + (size_t)gi * 64 + 32 * sq);
#pragma unroll
                for (int i = 0; i < 8; i++) v[i] = xr[i];
            } else {
#pragma unroll
                for (int i = 0; i < 8; i++) v[i] = make_float4(0.f, 0.f, 0.f, 0.f);
            }
            cvt_store_half(Ah, Al, sr, sq, v);
        }
        __syncthreads();

        // x_sum partial: thread sums column cc over rows rp::4
#pragma unroll 8
        for (int i = 0; i < 32; i++) {
            int r = rp + 4 * i;
            float vh = __bfloat162float(*reinterpret_cast<__nv_bfloat16*>(Ah + r * (LDA * 2) + 2 * cc));
            float vl = __bfloat162float(*reinterpret_cast<__nv_bfloat16*>(Al + r * (LDA * 2) + 2 * cc));
            xacc += vh + vl;
        }

        // M += A^T A  (3-split: AhT Ah + AhT Al + AlT Ah)
        const __nv_bfloat16* ah16 = reinterpret_cast<const __nv_bfloat16*>(Ah);
        const __nv_bfloat16* al16 = reinterpret_cast<const __nv_bfloat16*>(Al);
#pragma unroll
        for (int k = 0; k < 8; k++) {
            FragAT ath, atl;  // A^T tile (wi, k): col_major load from A[16k][16wi]
            wmma::load_matrix_sync(ath, ah16 + (size_t)(16 * k) * LDA + 16 * wi, LDA);
            wmma::load_matrix_sync(atl, al16 + (size_t)(16 * k) * LDA + 16 * wi, LDA);
            FragB bh0, bl0, bh1, bl1;  // A tiles (k, wj), (k, wj+1)
            wmma::load_matrix_sync(bh0, ah16 + (size_t)(16 * k) * LDA + 16 * wj, LDA);
            wmma::load_matrix_sync(bl0, al16 + (size_t)(16 * k) * LDA + 16 * wj, LDA);
            wmma::load_matrix_sync(bh1, ah16 + (size_t)(16 * k) * LDA + 16 * (wj + 1), LDA);
            wmma::load_matrix_sync(bl1, al16 + (size_t)(16 * k) * LDA + 16 * (wj + 1), LDA);
            wmma::mma_sync(m0, ath, bh0, m0);
            wmma::mma_sync(m0, ath, bl0, m0);
            wmma::mma_sync(m0, atl, bh0, m0);
            wmma::mma_sync(m1, ath, bh1, m1);
            wmma::mma_sync(m1, ath, bl1, m1);
            wmma::mma_sync(m1, atl, bh1, m1);
        }
        __syncthreads();   // reads done before next staging
    }

    // reduce x_sum
    xs[rp * 64 + cc] = xacc;
    __syncthreads();
    if (t < 64)
        d_xsum[(size_t)g * 64 + t] = xs[t] + xs[64 + t] + xs[128 + t] + xs[192 + t];

    // store M tiles (row-major, stride 64) to global
    float* Mg = d_M + (size_t)g * 4096;
    wmma::store_matrix_sync(Mg + (size_t)(16 * wi) * 64 + 16 * wj,       m0, 64, wmma::mem_row_major);
    wmma::store_matrix_sync(Mg + (size_t)(16 * wi) * 64 + 16 * (wj + 1), m1, 64, wmma::mem_row_major);
}

// ---------------------------------------------------------------------------
// Kernel 2: finalize — per group: T = M @ W (wmma 3-split), q_c = sum_k W[k,c]T[k,c],
// mean_c = (x_sum @ W)_c / cnt, scale/shift tables.
// smem: Mh 9216, Ml 9216, Wh 9216, Wl 9216, T 64*72*4=18432 -> 55296
// ---------------------------------------------------------------------------
#define FIN_SMEM 55296

__global__ __launch_bounds__(256, 3) void finalize_kernel(const float* __restrict__ Wfc) {
    extern __shared__ char smem[];
    char*  Mh = smem;
    char*  Ml = smem + 9216;
    char*  Wh = smem + 18432;
    char*  Wl = smem + 27648;
    float* T  = reinterpret_cast<float*>(smem + 36864);

    int t = threadIdx.x, w = t >> 5;
    int g   = blockIdx.x;
    int cnt = d_offsets[g + 1] - d_offsets[g];
    if (cnt == 0) return;

    // W hi/lo images -> smem
    for (int i = t; i < 2048; i += 256) {
        int k = i >> 5, j = i & 31;
        int b2 = k * (LDA * 2) + 4 * j;
        *reinterpret_cast<uint32_t*>(Wh + b2) = d_Wh32[i];
        *reinterpret_cast<uint32_t*>(Wl + b2) = d_Wl32[i];
    }
    // M -> bf16 hi/lo smem
    const float* Mg = d_M + (size_t)g * 4096;
    for (int i = t; i < 4096; i += 256) {
        float m = Mg[i];
        __nv_bfloat16 h = __float2bfloat16(m);
        __nv_bfloat16 l = __float2bfloat16(m - __bfloat162float(h));
        int r = i >> 6, c2 = i & 63;
        *reinterpret_cast<__nv_bfloat16*>(Mh + r * (LDA * 2) + 2 * c2) = h;
        *reinterpret_cast<__nv_bfloat16*>(Ml + r * (LDA * 2) + 2 * c2) = l;
    }
    __syncthreads();

    // T = M @ W, warp w: tiles (wi, wj), (wi, wj+1)
    {
        int wi = w >> 1, wj = (w & 1) * 2;
        const __nv_bfloat16* mh16 = reinterpret_cast<const __nv_bfloat16*>(Mh);
        const __nv_bfloat16* ml16 = reinterpret_cast<const __nv_bfloat16*>(Ml);
        const __nv_bfloat16* wh16 = reinterpret_cast<const __nv_bfloat16*>(Wh);
        const __nv_bfloat16* wl16 = reinterpret_cast<const __nv_bfloat16*>(Wl);
        FragC t0, t1;
        wmma::fill_fragment(t0, 0.f);
        wmma::fill_fragment(t1, 0.f);
#pragma unroll
        for (int k = 0; k < 4; k++) {
            FragA ah, al;
            wmma::load_matrix_sync(ah, mh16 + (size_t)(16 * wi) * LDA + 16 * k, LDA);
            wmma::load_matrix_sync(al, ml16 + (size_t)(16 * wi) * LDA + 16 * k, LDA);
            FragB bh0, bl0, bh1, bl1;
            wmma::load_matrix_sync(bh0, wh16 + (size_t)(16 * k) * LDA + 16 * wj, LDA);
            wmma::load_matrix_sync(bl0, wl16 + (size_t)(16 * k) * LDA + 16 * wj, LDA);
            wmma::load_matrix_sync(bh1, wh16 + (size_t)(16 * k) * LDA + 16 * (wj + 1), LDA);
            wmma::load_matrix_sync(bl1, wl16 + (size_t)(16 * k) * LDA + 16 * (wj + 1), LDA);
            wmma::mma_sync(t0, ah, bh0, t0);
            wmma::mma_sync(t0, ah, bl0, t0);
            wmma::mma_sync(t0, al, bh0, t0);
            wmma::mma_sync(t1, ah, bh1, t1);
            wmma::mma_sync(t1, ah, bl1, t1);
            wmma::mma_sync(t1, al, bh1, t1);
        }
        wmma::store_matrix_sync(T + (size_t)(16 * wi) * LDA + 16 * wj,       t0, LDA, wmma::mem_row_major);
        wmma::store_matrix_sync(T + (size_t)(16 * wi) * LDA + 16 * (wj + 1), t1, LDA, wmma::mem_row_major);
    }
    __syncthreads();

    if (t < 64) {
        int c = t;
        float inv = 1.0f / (float)cnt;
        float mdot = 0.f, q = 0.f;
#pragma unroll 8
        for (int k = 0; k < 64; k++) {
            float wk = __ldg(&Wfc[k * 64 + c]);
            mdot = fmaf(__ldg(&d_xsum[(size_t)g * 64 + k]), wk, mdot);
            q    = fmaf(wk, T[k * LDA + c], q);
        }
        float mean = mdot * inv;
        float var  = fmaxf(q * inv - mean * mean, 0.f);
        float sc   = __ldg(&d_sig[(size_t)g * 64 + t]) * rsqrtf(var + 1e-14f);
        d_scale[(size_t)g * 64 + t] = sc;
        d_shift[(size_t)g * 64 + t] = __ldg(&d_mu[(size_t)g * 64 + t]) - mean * sc;
    }
}

// ---------------------------------------------------------------------------
// Kernel 3: dense apply — row-order x read, wmma h, scale/shift lookup by seg
// (2MB tables, L2-resident), ReLU, row-order out write. NO scattered 256B rows.
// smem: Wh 9216, Wl 9216, Ah 18432, Al 18432, H 128*72*4=36864 -> 92160
// ---------------------------------------------------------------------------
#define APL_SMEM 92160

__global__ __launch_bounds__(256, 2) void apply_dense_kernel(const float* __restrict__ x,
                                                             const int* __restrict__ seg,
                                                             float* __restrict__ out, int n) {
    extern __shared__ char smem[];
    char*  Wh = smem;
    char*  Wl = smem + 9216;
    char*  Ah = smem + 18432;
    char*  Al = smem + 36864;
    float* sH = reinterpret_cast<float*>(smem + 55296);

    int t = threadIdx.x, w = t >> 5;
    int base = blockIdx.x * 128;

    for (int i = t; i < 2048; i += 256) {
        int k = i >> 5, j = i & 31;
        int b2 = k * (LDA * 2) + 4 * j;
        *reinterpret_cast<uint32_t*>(Wh + b2) = d_Wh32[i];
        *reinterpret_cast<uint32_t*>(Wl + b2) = d_Wl32[i];
    }
    // stage 128 DENSE rows
    {
        int sr = t >> 1, sq = t & 1;
        int row = base + sr;
        float4 v[8];
        if (row < n) {
            const float4* xr = reinterpret_cast<const float4*>(x + (size_t)row * 64 + 32 * sq);
#pragma unroll
            for (int i = 0; i < 8; i++) v[i] = xr[i];
        } else {
#pragma unroll
            for (int i = 0; i < 8; i++) v[i] = make_float4(0.f, 0.f, 0.f, 0.f);
        }
        cvt_store_half(Ah, Al, sr, sq, v);
    }
    __syncthreads();

    // h = x @ W (3-split), warp w: rows 16w..16w+15
    {
        const __nv_bfloat16* ah16 = reinterpret_cast<const __nv_bfloat16*>(Ah);
        const __nv_bfloat16* al16 = reinterpret_cast<const __nv_bfloat16*>(Al);
        const __nv_bfloat16* wh16 = reinterpret_cast<const __nv_bfloat16*>(Wh);
        const __nv_bfloat16* wl16 = reinterpret_cast<const __nv_bfloat16*>(Wl);
        FragA ah[4], al[4];
#pragma unroll
        for (int k = 0; k < 4; k++) {
            wmma::load_matrix_sync(ah[k], ah16 + (size_t)(16 * w) * LDA + 16 * k, LDA);
            wmma::load_matrix_sync(al[k], al16 + (size_t)(16 * w) * LDA + 16 * k, LDA);
        }
        FragC acc[4];
#pragma unroll
        for (int ct = 0; ct < 4; ct++) wmma::fill_fragment(acc[ct], 0.f);
#pragma unroll
        for (int ct = 0; ct < 4; ct++) {
#pragma unroll
            for (int k = 0; k < 4; k++) {
                FragB bh;
                wmma::load_matrix_sync(bh, wh16 + (size_t)(16 * k) * LDA + 16 * ct, LDA);
                wmma::mma_sync(acc[ct], ah[k], bh, acc[ct]);
                wmma::mma_sync(acc[ct], al[k], bh, acc[ct]);
            }
#pragma unroll
            for (int k = 0; k < 4; k++) {
                FragB bl;
                wmma::load_matrix_sync(bl, wl16 + (size_t)(16 * k) * LDA + 16 * ct, LDA);
                wmma::mma_sync(acc[ct], ah[k], bl, acc[ct]);
            }
        }
#pragma unroll
        for (int ct = 0; ct < 4; ct++)
            wmma::store_matrix_sync(sH + (size_t)(16 * w) * LDA + 16 * ct, acc[ct],
                                    LDA, wmma::mem_row_major);
    }
    __syncthreads();

    // apply: thread (c4 = t&15, rq = t>>4) handles rows rq::16, channel quad c4
    {
        int c4 = t & 15, rq = t >> 4;
        const float4* scl4 = reinterpret_cast<const float4*>(d_scale);
        const float4* shf4 = reinterpret_cast<const float4*>(d_shift);
        float4* o4 = reinterpret_cast<float4*>(out);
#pragma unroll
        for (int i = 0; i < 8; i++) {
            int r = rq + 16 * i;
            int row = base + r;
            if (row < n) {
                int g = __ldg(&seg[row]);
                float4 sc = scl4[(size_t)g * 16 + c4];
                float4 sh = shf4[(size_t)g * 16 + c4];
                float4 v  = *reinterpret_cast<float4*>(&sH[(size_t)r * LDA + 4 * c4]);
                float4 o;
                o.x = fmaxf(fmaf(v.x, sc.x, sh.x), 0.f);
                o.y = fmaxf(fmaf(v.y, sc.y, sh.y), 0.f);
                o.z = fmaxf(fmaf(v.z, sc.z, sh.z), 0.f);
                o.w = fmaxf(fmaf(v.w, sc.w, sh.w), 0.f);
                o4[(size_t)row * 16 + c4] = o;
            }
        }
    }
}

// ---------------------------------------------------------------------------
extern "C" void kernel_launch(void* const* d_in, const int* in_sizes, int n_in,
                              void* d_out, int out_size) {
    int wi = (n_in >= 10) ? 4 : 3;
    const float* x    = (const float*)d_in[0];
    const float* feat = (const float*)d_in[1];
    const int*   seg  = (const int*)d_in[2];
    const float* Wfc  = (const float*)d_in[wi + 0];
    const float* Wmu  = (const float*)d_in[wi + 2];
    const float* bmu  = (const float*)d_in[wi + 3];
    const float* Wsg  = (const float*)d_in[wi + 4];
    const float* bsg  = (const float*)d_in[wi + 5];
    float* out = (float*)d_out;

    int n = in_sizes[0] / 64;
    int G = in_sizes[1] / 128;

    cudaFuncSetAttribute(moment_kernel,   cudaFuncAttributeMaxDynamicSharedMemorySize, MOM_SMEM);
    cudaFuncSetAttribute(finalize_kernel, cudaFuncAttributeMaxDynamicSharedMemorySize, FIN_SMEM);
    cudaFuncSetAttribute(apply_dense_kernel, cudaFuncAttributeMaxDynamicSharedMemorySize, APL_SMEM);

    int q = (n + 3) / 4;
    musig_init_kernel<<<(G + 3) / 4, 256>>>(feat, Wmu, bmu, Wsg, bsg, Wfc, G);
    hist_kernel<<<(q + 255) / 256, 256>>>(seg, n);
    scan_kernel<<<1, 1024>>>(G);
    scatter_kernel<<<(q + 255) / 256, 256>>>(seg, n);
    moment_kernel<<<G, 256, MOM_SMEM>>>(x);
    finalize_kernel<<<G, 256, FIN_SMEM>>>(Wfc);
    apply_dense_kernel<<<(n + 127) / 128, 256, APL_SMEM>>>(x, seg, out, n);
}

// round 17
// speedup vs baseline: 1.1791x; 1.1791x over previous
#include <cuda_runtime.h>
#include <cuda_bf16.h>
#include <mma.h>
#include <stdint.h>

using namespace nvcuda;

// Problem constants (fixed benchmark): N=1e6, IN_C=OUT_C=64, FEAT_C=128, G=4096
#define N_MAX 1000000
#define G_MAX 4096

__device__ int      d_count[G_MAX];
__device__ int      d_offsets[G_MAX + 1];
__device__ int      d_rank[N_MAX];
__device__ int      d_order[N_MAX];
__device__ int      d_gsort[N_MAX];        // group id at each sorted position
__device__ float    d_mu[G_MAX * 64];
__device__ float    d_sig[G_MAX * 64];
__device__ uint32_t d_Wh32[2048];          // bf16 hi image of W [64k][64n] as u32 pairs
__device__ uint32_t d_Wl32[2048];          // bf16 lo image
__device__ float    d_gsum[G_MAX * 64];    // per-group channel sums of h
__device__ float    d_gsq[G_MAX * 64];     // per-group channel sums of h^2
__device__ float    d_scale[G_MAX * 64];
__device__ float    d_shift[G_MAX * 64];

// ---------------------------------------------------------------------------
// Preprocessing
// ---------------------------------------------------------------------------
__global__ void musig_init_kernel(const float* __restrict__ feat,
                                  const float* __restrict__ Wmu, const float* __restrict__ bmu,
                                  const float* __restrict__ Wsg, const float* __restrict__ bsg,
                                  const float* __restrict__ Wfc, int G) {
    int gid = blockIdx.x * blockDim.x + threadIdx.x;
    if (gid < G) d_count[gid] = 0;
    if (gid < G * 64) { d_gsum[gid] = 0.f; d_gsq[gid] = 0.f; }
    if (gid < 2048) {  // pair (k, 2j)/(k, 2j+1)
        int k = gid >> 5, j = gid & 31;
        float w0 = Wfc[k * 64 + 2 * j];
        float w1 = Wfc[k * 64 + 2 * j + 1];
        __nv_bfloat16 h0 = __float2bfloat16(w0);
        __nv_bfloat16 h1 = __float2bfloat16(w1);
        __nv_bfloat16 l0 = __float2bfloat16(w0 - __bfloat162float(h0));
        __nv_bfloat16 l1 = __float2bfloat16(w1 - __bfloat162float(h1));
        d_Wh32[gid] = (uint32_t)__bfloat16_as_ushort(h0) | ((uint32_t)__bfloat16_as_ushort(h1) << 16);
        d_Wl32[gid] = (uint32_t)__bfloat16_as_ushort(l0) | ((uint32_t)__bfloat16_as_ushort(l1) << 16);
    }

    __shared__ float sF[4][128];
    int t  = threadIdx.x;
    int g0 = blockIdx.x * 4;
    for (int i = t; i < 512; i += 256) {
        int gl = i >> 7, k = i & 127;
        int g  = g0 + gl;
        sF[gl][k] = (g < G) ? feat[(size_t)g * 128 + k] : 0.f;
    }
    __syncthreads();
    int gl = t >> 6, c = t & 63;
    int g  = g0 + gl;
    if (g >= G) return;
    float am = bmu[c], as = bsg[c];
#pragma unroll 4
    for (int k = 0; k < 128; k++) {
        float f = sF[gl][k];
        am = fmaf(f, Wmu[k * 64 + c], am);
        as = fmaf(f, Wsg[k * 64 + c], as);
    }
    d_mu[(size_t)g * 64 + c]  = am;
    d_sig[(size_t)g * 64 + c] = as;
}

__global__ void hist_kernel(const int* __restrict__ seg, int n) {
    int i = blockIdx.x * blockDim.x + threadIdx.x;
    int base = i * 4;
    if (base + 3 < n) {
        int4 s = *reinterpret_cast<const int4*>(seg + base);
        int r0 = atomicAdd(&d_count[s.x], 1);
        int r1 = atomicAdd(&d_count[s.y], 1);
        int r2 = atomicAdd(&d_count[s.z], 1);
        int r3 = atomicAdd(&d_count[s.w], 1);
        *reinterpret_cast<int4*>(d_rank + base) = make_int4(r0, r1, r2, r3);
    } else {
        for (int j = base; j < n; j++)
            d_rank[j] = atomicAdd(&d_count[seg[j]], 1);
    }
}

__global__ void scan_kernel(int G) {
    __shared__ int wsum[32];
    __shared__ int wpre[32];
    const unsigned full = 0xffffffffu;
    int t = threadIdx.x, lane = t & 31, w = t >> 5;
    int v[4];
    int s = 0;
#pragma unroll
    for (int i = 0; i < 4; i++) {
        int g = 4 * t + i;
        v[i] = (g < G) ? d_count[g] : 0;
        s += v[i];
    }
    int sc = s;
#pragma unroll
    for (int off = 1; off < 32; off <<= 1) {
        int o = __shfl_up_sync(full, sc, off);
        if (lane >= off) sc += o;
    }
    if (lane == 31) wsum[w] = sc;
    __syncthreads();
    if (w == 0) {
        int ws = wsum[lane];
        int p = ws;
#pragma unroll
        for (int off = 1; off < 32; off <<= 1) {
            int o = __shfl_up_sync(full, p, off);
            if (lane >= off) p += o;
        }
        wpre[lane] = p - ws;
    }
    __syncthreads();
    int excl = wpre[w] + sc - s;
#pragma unroll
    for (int i = 0; i < 4; i++) {
        int g = 4 * t + i;
        if (g < G) {
            d_offsets[g] = excl;
            excl += v[i];
        }
    }
    if (t == 1023) d_offsets[G] = excl;
}

// position = group offset + rank; also record group id at sorted position
__global__ void scatter_kernel(const int* __restrict__ seg, int n) {
    int i = blockIdx.x * blockDim.x + threadIdx.x;
    int base = i * 4;
    if (base + 3 < n) {
        int4 s = *reinterpret_cast<const int4*>(seg + base);
        int4 r = *reinterpret_cast<const int4*>(d_rank + base);
        int p0 = d_offsets[s.x] + r.x;
        int p1 = d_offsets[s.y] + r.y;
        int p2 = d_offsets[s.z] + r.z;
        int p3 = d_offsets[s.w] + r.w;
        d_order[p0] = base;     d_gsort[p0] = s.x;
        d_order[p1] = base + 1; d_gsort[p1] = s.y;
        d_order[p2] = base + 2; d_gsort[p2] = s.z;
        d_order[p3] = base + 3; d_gsort[p3] = s.w;
    } else {
        for (int j = base; j < n; j++) {
            int g = seg[j];
            int p = d_offsets[g] + d_rank[j];
            d_order[p] = j;
            d_gsort[p] = g;
        }
    }
}

// ---------------------------------------------------------------------------
// Common: convert a staged x row-half into bf16 hi/lo smem (stride LDA=72)
// ---------------------------------------------------------------------------
#define LDA 72

__device__ __forceinline__ void cvt_store_half(char* Ah, char* Al, int sr, int sq,
                                               const float4 v[8]) {
    uint32_t uh[16], ul[16];
#pragma unroll
    for (int i = 0; i < 8; i++) {
        float f0 = v[i].x, f1 = v[i].y, f2 = v[i].z, f3 = v[i].w;
        __nv_bfloat16 h0 = __float2bfloat16(f0), h1 = __float2bfloat16(f1);
        __nv_bfloat16 h2 = __float2bfloat16(f2), h3 = __float2bfloat16(f3);
        __nv_bfloat16 l0 = __float2bfloat16(f0 - __bfloat162float(h0));
        __nv_bfloat16 l1 = __float2bfloat16(f1 - __bfloat162float(h1));
        __nv_bfloat16 l2 = __float2bfloat16(f2 - __bfloat162float(h2));
        __nv_bfloat16 l3 = __float2bfloat16(f3 - __bfloat162float(h3));
        uh[2 * i]     = (uint32_t)__bfloat16_as_ushort(h0) | ((uint32_t)__bfloat16_as_ushort(h1) << 16);
        uh[2 * i + 1] = (uint32_t)__bfloat16_as_ushort(h2) | ((uint32_t)__bfloat16_as_ushort(h3) << 16);
        ul[2 * i]     = (uint32_t)__bfloat16_as_ushort(l0) | ((uint32_t)__bfloat16_as_ushort(l1) << 16);
        ul[2 * i + 1] = (uint32_t)__bfloat16_as_ushort(l2) | ((uint32_t)__bfloat16_as_ushort(l3) << 16);
    }
    int b2 = sr * (LDA * 2) + 64 * sq;
#pragma unroll
    for (int i = 0; i < 4; i++) {
        *reinterpret_cast<uint4*>(Ah + b2 + 16 * i) =
            make_uint4(uh[4 * i], uh[4 * i + 1], uh[4 * i + 2], uh[4 * i + 3]);
        *reinterpret_cast<uint4*>(Al + b2 + 16 * i) =
            make_uint4(ul[4 * i], ul[4 * i + 1], ul[4 * i + 2], ul[4 * i + 3]);
    }
}

typedef wmma::fragment<wmma::matrix_a, 16, 16, 16, __nv_bfloat16, wmma::row_major> FragA;
typedef wmma::fragment<wmma::matrix_b, 16, 16, 16, __nv_bfloat16, wmma::row_major> FragB;
typedef wmma::fragment<wmma::accumulator, 16, 16, 16, float> FragC;

// 3-split h GEMM for 128 staged rows; result into sH (stride LDA floats)
__device__ __forceinline__ void gemm128(const char* Wh, const char* Wl,
                                        const char* Ah, const char* Al,
                                        float* sH, int w) {
    const __nv_bfloat16* ah16 = reinterpret_cast<const __nv_bfloat16*>(Ah);
    const __nv_bfloat16* al16 = reinterpret_cast<const __nv_bfloat16*>(Al);
    const __nv_bfloat16* wh16 = reinterpret_cast<const __nv_bfloat16*>(Wh);
    const __nv_bfloat16* wl16 = reinterpret_cast<const __nv_bfloat16*>(Wl);
    FragA ah[4], al[4];
#pragma unroll
    for (int k = 0; k < 4; k++) {
        wmma::load_matrix_sync(ah[k], ah16 + (size_t)(16 * w) * LDA + 16 * k, LDA);
        wmma::load_matrix_sync(al[k], al16 + (size_t)(16 * w) * LDA + 16 * k, LDA);
    }
    FragC acc[4];
#pragma unroll
    for (int ct = 0; ct < 4; ct++) wmma::fill_fragment(acc[ct], 0.f);
#pragma unroll
    for (int ct = 0; ct < 4; ct++) {
#pragma unroll
        for (int k = 0; k < 4; k++) {
            FragB bh;
            wmma::load_matrix_sync(bh, wh16 + (size_t)(16 * k) * LDA + 16 * ct, LDA);
            wmma::mma_sync(acc[ct], ah[k], bh, acc[ct]);
            wmma::mma_sync(acc[ct], al[k], bh, acc[ct]);
        }
#pragma unroll
        for (int k = 0; k < 4; k++) {
            FragB bl;
            wmma::load_matrix_sync(bl, wl16 + (size_t)(16 * k) * LDA + 16 * ct, LDA);
            wmma::mma_sync(acc[ct], ah[k], bl, acc[ct]);
        }
    }
#pragma unroll
    for (int ct = 0; ct < 4; ct++)
        wmma::store_matrix_sync(sH + (size_t)(16 * w) * LDA + 16 * ct, acc[ct],
                                LDA, wmma::mem_row_major);
}

// ---------------------------------------------------------------------------
// Kernel 1: stats GEMM over SORTED rows. Gather x via d_order (only scattered
// traffic in the pipeline), 3-split wmma h -> smem, per-channel stats over
// contiguous sorted rows, segment-flush to global atomics. NO h global buffer.
// smem: Wh 9216 | Wl 9216 | Ah 18432 | Al 18432 | sH 36864 | sG 512 = 92672
// ---------------------------------------------------------------------------
#define SG_SMEM 92672

__global__ __launch_bounds__(256, 2) void stats_gemm_kernel(const float* __restrict__ x,
                                                            int n) {
    extern __shared__ char smem[];
    char*  Wh = smem;
    char*  Wl = smem + 9216;
    char*  Ah = smem + 18432;
    char*  Al = smem + 36864;
    float* sH = reinterpret_cast<float*>(smem + 55296);
    int*   sG = reinterpret_cast<int*>(smem + 92160);

    int t = threadIdx.x, w = t >> 5;
    int base = blockIdx.x * 128;

    for (int i = t; i < 2048; i += 256) {
        int k = i >> 5, j = i & 31;
        int b2 = k * (LDA * 2) + 4 * j;
        *reinterpret_cast<uint32_t*>(Wh + b2) = d_Wh32[i];
        *reinterpret_cast<uint32_t*>(Wl + b2) = d_Wl32[i];
    }
    if (t < 128) sG[t] = (base + t < n) ? d_gsort[base + t] : -1;

    // stage 128 sorted rows (gather)
    {
        int sr = t >> 1, sq = t & 1;
        int row = base + sr;
        float4 v[8];
        if (row < n) {
            int gi = __ldg(&d_order[row]);
            const float4* xr = reinterpret_cast<const float4*>(x + (size_t)gi * 64 + 32 * sq);
#pragma unroll
            for (int i = 0; i < 8; i++) v[i] = xr[i];
        } else {
#pragma unroll
            for (int i = 0; i < 8; i++) v[i] = make_float4(0.f, 0.f, 0.f, 0.f);
        }
        cvt_store_half(Ah, Al, t >> 1, sq, v);
    }
    __syncthreads();

    gemm128(Wh, Wl, Ah, Al, sH, w);
    __syncthreads();

    // stats: thread = (channel cc = t&63, quarter rp = t>>6 -> rows rp*32..+31,
    // CONTIGUOUS sorted rows -> monotone group changes, flush on boundary)
    {
        int cc = t & 63, rp = t >> 6;
        int r0 = rp * 32;
        float s1 = 0.f, s2 = 0.f;
        int curg = sG[r0];
#pragma unroll 4
        for (int r = r0; r < r0 + 32; r++) {
            int g = sG[r];
            if (g != curg) {
                if (curg >= 0) {
                    atomicAdd(&d_gsum[(size_t)curg * 64 + cc], s1);
                    atomicAdd(&d_gsq[(size_t)curg * 64 + cc],  s2);
                }
                curg = g; s1 = 0.f; s2 = 0.f;
            }
            if (g >= 0) {
                float h = sH[(size_t)r * LDA + cc];
                s1 += h;
                s2 = fmaf(h, h, s2);
            }
        }
        if (curg >= 0) {
            atomicAdd(&d_gsum[(size_t)curg * 64 + cc], s1);
            atomicAdd(&d_gsq[(size_t)curg * 64 + cc],  s2);
        }
    }
}

// ---------------------------------------------------------------------------
// Kernel 2: finalize scale/shift tables (one thread per (g, c))
// ---------------------------------------------------------------------------
__global__ void finalize_kernel(int G) {
    int idx = blockIdx.x * blockDim.x + threadIdx.x;
    if (idx >= G * 64) return;
    int g = idx >> 6;
    int cnt = d_offsets[g + 1] - d_offsets[g];
    if (cnt == 0) return;
    float inv  = 1.0f / (float)cnt;
    float mean = d_gsum[idx] * inv;
    float var  = fmaxf(d_gsq[idx] * inv - mean * mean, 0.f);
    float sc   = d_sig[idx] * rsqrtf(var + 1e-14f);
    d_scale[idx] = sc;
    d_shift[idx] = d_mu[idx] - mean * sc;
}

// ---------------------------------------------------------------------------
// Kernel 3: dense apply — row-order x read, recompute h via wmma, scale/shift
// lookup by seg (2MB tables, L2), ReLU, row-order out write. No scatter.
// smem: Wh 9216 | Wl 9216 | Ah 18432 | Al 18432 | sH 36864 = 92160
// ---------------------------------------------------------------------------
#define APL_SMEM 92160

__global__ __launch_bounds__(256, 2) void apply_dense_kernel(const float* __restrict__ x,
                                                             const int* __restrict__ seg,
                                                             float* __restrict__ out, int n) {
    extern __shared__ char smem[];
    char*  Wh = smem;
    char*  Wl = smem + 9216;
    char*  Ah = smem + 18432;
    char*  Al = smem + 36864;
    float* sH = reinterpret_cast<float*>(smem + 55296);

    int t = threadIdx.x, w = t >> 5;
    int base = blockIdx.x * 128;

    for (int i = t; i < 2048; i += 256) {
        int k = i >> 5, j = i & 31;
        int b2 = k * (LDA * 2) + 4 * j;
        *reinterpret_cast<uint32_t*>(Wh + b2) = d_Wh32[i];
        *reinterpret_cast<uint32_t*>(Wl + b2) = d_Wl32[i];
    }
    // stage 128 DENSE rows
    {
        int sr = t >> 1, sq = t & 1;
        int row = base + sr;
        float4 v[8];
        if (row < n) {
            const float4* xr = reinterpret_cast<const float4*>(x + (size_t)row * 64 + 32 * sq);
#pragma unroll
            for (int i = 0; i < 8; i++) v[i] = xr[i];
        } else {
#pragma unroll
            for (int i = 0; i < 8; i++) v[i] = make_float4(0.f, 0.f, 0.f, 0.f);
        }
        cvt_store_half(Ah, Al, sr, sq, v);
    }
    __syncthreads();

    gemm128(Wh, Wl, Ah, Al, sH, w);
    __syncthreads();

    // apply: thread (c4 = t&15, rq = t>>4) handles rows rq::16, channel quad c4
    {
        int c4 = t & 15, rq = t >> 4;
        const float4* scl4 = reinterpret_cast<const float4*>(d_scale);
        const float4* shf4 = reinterpret_cast<const float4*>(d_shift);
        float4* o4 = reinterpret_cast<float4*>(out);
#pragma unroll
        for (int i = 0; i < 8; i++) {
            int r = rq + 16 * i;
            int row = base + r;
            if (row < n) {
                int g = __ldg(&seg[row]);
                float4 sc = scl4[(size_t)g * 16 + c4];
                float4 sh = shf4[(size_t)g * 16 + c4];
                float4 v  = *reinterpret_cast<float4*>(&sH[(size_t)r * LDA + 4 * c4]);
                float4 o;
                o.x = fmaxf(fmaf(v.x, sc.x, sh.x), 0.f);
                o.y = fmaxf(fmaf(v.y, sc.y, sh.y), 0.f);
                o.z = fmaxf(fmaf(v.z, sc.z, sh.z), 0.f);
                o.w = fmaxf(fmaf(v.w, sc.w, sh.w), 0.f);
                o4[(size_t)row * 16 + c4] = o;
            }
        }
    }
}

// ---------------------------------------------------------------------------
extern "C" void kernel_launch(void* const* d_in, const int* in_sizes, int n_in,
                              void* d_out, int out_size) {
    int wi = (n_in >= 10) ? 4 : 3;
    const float* x    = (const float*)d_in[0];
    const float* feat = (const float*)d_in[1];
    const int*   seg  = (const int*)d_in[2];
    const float* Wfc  = (const float*)d_in[wi + 0];
    const float* Wmu  = (const float*)d_in[wi + 2];
    const float* bmu  = (const float*)d_in[wi + 3];
    const float* Wsg  = (const float*)d_in[wi + 4];
    const float* bsg  = (const float*)d_in[wi + 5];
    float* out = (float*)d_out;

    int n = in_sizes[0] / 64;
    int G = in_sizes[1] / 128;

    cudaFuncSetAttribute(stats_gemm_kernel, cudaFuncAttributeMaxDynamicSharedMemorySize, SG_SMEM);
    cudaFuncSetAttribute(apply_dense_kernel, cudaFuncAttributeMaxDynamicSharedMemorySize, APL_SMEM);

    int q = (n + 3) / 4;
    int nblk = (n + 127) / 128;
    musig_init_kernel<<<(G + 3) / 4, 256>>>(feat, Wmu, bmu, Wsg, bsg, Wfc, G);
    hist_kernel<<<(q + 255) / 256, 256>>>(seg, n);
    scan_kernel<<<1, 1024>>>(G);
    scatter_kernel<<<(q + 255) / 256, 256>>>(seg, n);
    stats_gemm_kernel<<<nblk, 256, SG_SMEM>>>(x, n);
    finalize_kernel<<<(G * 64 + 255) / 256, 256>>>(G);
    apply_dense_kernel<<<nblk, 256, APL_SMEM>>>(x, seg, out, n);
}